// round 4
// baseline (speedup 1.0000x reference)
#include <cuda_runtime.h>
#include <cuda.h>
#include <dlfcn.h>
#include <math.h>
#include <stdint.h>

// ---------------- problem constants ----------------
#define T_DIM 1024
#define B_DIM 8
#define C_DIM 1024
#define F_DIM 4096
#define H_DIM 16
#define K_TAPS 15
#define M_DIM (T_DIM * B_DIM)   // 8192
#define NPAD 256
#define LN_EPS 1e-5f

// tcgen05 GEMM tile config: 256(M) x 256(N), dual 128-row MMA, 3-stage pipeline
#define BM 256
#define BN 256
#define BK 32                            // floats per k-chunk (128 bytes)
#define STAGES 3
#define CHUNK_A_BYTES (BM * BK * 4)      // 32768
#define CHUNK_B_BYTES (BN * BK * 4)      // 32768
#define CHUNK_BYTES (CHUNK_A_BYTES + CHUNK_B_BYTES)   // 65536
#define SMEM_BYTES (1024 + STAGES * CHUNK_BYTES)      // 197632

// dynconv tiling
#define TT 32                            // timesteps per block
#define HALO (K_TAPS - 1)                // 14
#define XS_ROWS (TT + HALO)              // 46
#define DC_SMEM ((XS_ROWS * C_DIM + TT * (H_DIM * K_TAPS) + 64) * 4)

// arch-specific feature gate (tcgen05 only on the sm_103a pass)
#if defined(__CUDA_ARCH_FEAT_SM103_ALL) || defined(__CUDA_ARCH_FEAT_SM100_ALL) || \
    (defined(__CUDA_ARCH_SPECIFIC__) && (__CUDA_ARCH_SPECIFIC__ >= 1000)) ||      \
    (defined(__CUDA_ARCH_FAMILY_SPECIFIC__) && (__CUDA_ARCH_FAMILY_SPECIFIC__ >= 1000))
#define TC_OK 1
#else
#define TC_OK 0
#endif

// ---------------- scratch (device globals) ----------------
__device__ float g_wlinT[NPAD * C_DIM];                 // [256,1024] tf32-rounded
__device__ float g_fc1wT[(size_t)F_DIM * C_DIM];        // [4096,1024] tf32-rounded
__device__ float g_fc2wT[(size_t)C_DIM * F_DIM];        // [1024,4096] tf32-rounded
__device__ float g_wraw[(size_t)M_DIM * NPAD];          // conv logits
__device__ float g_y[(size_t)M_DIM * C_DIM];            // post-LN (exact fp32)
__device__ float g_yrn[(size_t)M_DIM * C_DIM];          // post-LN (tf32-rounded)
__device__ float g_h[(size_t)M_DIM * F_DIM];            // fc1 output (tf32-rounded)

// ---------------- helpers ----------------
__device__ __forceinline__ float to_tf32(float x) {
    float r;
    asm("cvt.rna.tf32.f32 %0, %1;" : "=f"(r) : "f"(x));
    return r;
}
__device__ __forceinline__ uint32_t smem_u32(const void* p) {
    uint32_t a;
    asm("{ .reg .u64 t; cvta.to.shared.u64 t, %1; cvt.u32.u64 %0, t; }" : "=r"(a) : "l"(p));
    return a;
}
__device__ __forceinline__ uint32_t elect_one() {
    uint32_t p;
    asm volatile("{ .reg .pred p; elect.sync _|p, 0xFFFFFFFF; selp.b32 %0, 1, 0, p; }" : "=r"(p));
    return p;
}
__device__ __forceinline__ void mbar_init(uint32_t a, uint32_t cnt) {
    asm volatile("mbarrier.init.shared.b64 [%0], %1;" :: "r"(a), "r"(cnt) : "memory");
}
__device__ __forceinline__ void mbar_expect_tx(uint32_t a, uint32_t bytes) {
    asm volatile("mbarrier.arrive.expect_tx.shared.b64 _, [%0], %1;" :: "r"(a), "r"(bytes) : "memory");
}
__device__ __forceinline__ void mbar_wait(uint32_t a, uint32_t parity) {
    uint32_t done;
    asm volatile(
        "{ .reg .pred p;\n\t"
        "mbarrier.try_wait.parity.acquire.cta.shared::cta.b64 p, [%1], %2;\n\t"
        "selp.b32 %0, 1, 0, p; }" : "=r"(done) : "r"(a), "r"(parity) : "memory");
    if (!done) {
        asm volatile(
            "{ .reg .pred P1;\n\t"
            "WL_%=:\n\t"
            "mbarrier.try_wait.parity.acquire.cta.shared::cta.b64 P1, [%0], %1, 0x989680;\n\t"
            "@P1 bra.uni WD_%=;\n\t"
            "bra.uni WL_%=;\n\t"
            "WD_%=: }" :: "r"(a), "r"(parity) : "memory");
    }
}
#if TC_OK
__device__ __forceinline__ void tma_2d(uint32_t dst, const void* map, int cx, int cy, uint32_t mbar) {
    asm volatile(
        "cp.async.bulk.tensor.2d.shared::cta.global.tile.mbarrier::complete_tx::bytes "
        "[%0], [%1, {%2, %3}], [%4];"
        :: "r"(dst), "l"(map), "r"(cx), "r"(cy), "r"(mbar) : "memory");
}
__device__ __forceinline__ void mma_tf32_ss(uint32_t d, uint64_t adesc, uint64_t bdesc,
                                            uint32_t idesc, uint32_t en) {
    asm volatile(
        "{ .reg .pred p;\n\t"
        "setp.ne.u32 p, %4, 0;\n\t"
        "tcgen05.mma.cta_group::1.kind::tf32 [%0], %1, %2, %3, p; }"
        :: "r"(d), "l"(adesc), "l"(bdesc), "r"(idesc), "r"(en) : "memory");
}
__device__ __forceinline__ void tc_commit(uint32_t mbar) {
    asm volatile(
        "tcgen05.commit.cta_group::1.mbarrier::arrive::one.shared::cluster.b64 [%0];"
        :: "r"(mbar) : "memory");
}
#define TC_ALLOC(smem_addr, ncols) \
    asm volatile("tcgen05.alloc.cta_group::1.sync.aligned.shared::cta.b32 [%0], %1;" \
                 :: "r"(smem_addr), "r"(ncols) : "memory")
#define TC_RELINQ() \
    asm volatile("tcgen05.relinquish_alloc_permit.cta_group::1.sync.aligned;")
#define TC_DEALLOC(tmem, ncols) \
    asm volatile("tcgen05.dealloc.cta_group::1.sync.aligned.b32 %0, %1;" :: "r"(tmem), "r"(ncols))
#define TC_FENCE_AFTER()  asm volatile("tcgen05.fence::after_thread_sync;" ::: "memory")
#define TC_WAIT_LD()      asm volatile("tcgen05.wait::ld.sync.aligned;" ::: "memory")
#define TC_LD_X32(r, addr) \
    asm volatile("tcgen05.ld.sync.aligned.32x32b.x32.b32 " \
        "{%0, %1, %2, %3, %4, %5, %6, %7, %8, %9, %10, %11, %12, %13, %14, %15, " \
        " %16, %17, %18, %19, %20, %21, %22, %23, %24, %25, %26, %27, %28, %29, %30, %31}, [%32];" \
        : "=r"((r)[0]), "=r"((r)[1]), "=r"((r)[2]), "=r"((r)[3]), \
          "=r"((r)[4]), "=r"((r)[5]), "=r"((r)[6]), "=r"((r)[7]), \
          "=r"((r)[8]), "=r"((r)[9]), "=r"((r)[10]), "=r"((r)[11]), \
          "=r"((r)[12]), "=r"((r)[13]), "=r"((r)[14]), "=r"((r)[15]), \
          "=r"((r)[16]), "=r"((r)[17]), "=r"((r)[18]), "=r"((r)[19]), \
          "=r"((r)[20]), "=r"((r)[21]), "=r"((r)[22]), "=r"((r)[23]), \
          "=r"((r)[24]), "=r"((r)[25]), "=r"((r)[26]), "=r"((r)[27]), \
          "=r"((r)[28]), "=r"((r)[29]), "=r"((r)[30]), "=r"((r)[31]) \
        : "r"(addr))

__device__ __forceinline__ uint64_t smem_desc_sw128(uint32_t addr) {
    return ((uint64_t)2 << 61) | ((uint64_t)1 << 46) | ((uint64_t)64 << 32) |
           ((uint64_t)1 << 16) | (((uint64_t)addr >> 4) & 0x3FFF);
}
#define IDESC_TF32 ((1u << 4) | (2u << 7) | (2u << 10) | ((BN / 8) << 17) | ((128 / 16) << 24))
#endif  // TC_OK

// ================= tcgen05 tf32 GEMM, 256x256 tile =================
// C[M,N] = A[M,K] @ Bt[N,K]^T. Two 128-row MMAs per K-step into TMEM halves
// [0,256) and [256,512). 3-stage TMA pipeline. 256 threads.
// EPI: 0 plain, 1 bias+relu+tf32-round, 2 bias+residual
template <int EPI>
__global__ __launch_bounds__(256)
void tc_gemm(const __grid_constant__ CUtensorMap tmA,
             const __grid_constant__ CUtensorMap tmB,
             const float* __restrict__ bias, const float* __restrict__ res,
             float* __restrict__ C, int N, int NC) {
#if TC_OK
    extern __shared__ __align__(1024) char smem[];
    const int tid  = threadIdx.x;
    const int warp = tid >> 5;
    const int lane = tid & 31;

    uint32_t sb = (smem_u32(smem) + 1023u) & ~1023u;
    const uint32_t tmem_ptr_addr = sb;
    uint32_t mb_full[STAGES], mb_done[STAGES], bufA[STAGES], bufB[STAGES];
    #pragma unroll
    for (int s = 0; s < STAGES; s++) {
        mb_full[s] = sb + 8 + 8 * s;
        mb_done[s] = sb + 8 + 8 * STAGES + 8 * s;
        bufA[s] = sb + 1024 + s * CHUNK_BYTES;
        bufB[s] = bufA[s] + CHUNK_A_BYTES;
    }

    if (warp == 0) {
        TC_ALLOC(tmem_ptr_addr, 512);
        TC_RELINQ();
    }
    if (tid == 0) {
        #pragma unroll
        for (int s = 0; s < STAGES; s++) { mbar_init(mb_full[s], 1); mbar_init(mb_done[s], 1); }
    }
    __syncthreads();

    uint32_t tmem;
    asm volatile("ld.shared.b32 %0, [%1];" : "=r"(tmem) : "r"(tmem_ptr_addr));

    const int tile_m = blockIdx.y * BM;
    const int tile_n = blockIdx.x * BN;

    if (warp == 0 && elect_one()) {
        uint64_t ad0[STAGES], ad1[STAGES], bd[STAGES];
        int phf[STAGES], phd[STAGES];
        #pragma unroll
        for (int s = 0; s < STAGES; s++) {
            ad0[s] = smem_desc_sw128(bufA[s]);
            ad1[s] = smem_desc_sw128(bufA[s] + 128 * 128);   // rows 128..255
            bd[s]  = smem_desc_sw128(bufB[s]);
            phf[s] = 0; phd[s] = 0;
        }
        // prologue
        #pragma unroll
        for (int s = 0; s < STAGES; s++) {
            if (s < NC) {
                mbar_expect_tx(mb_full[s], CHUNK_BYTES);
                tma_2d(bufA[s], &tmA, s * BK, tile_m, mb_full[s]);
                tma_2d(bufB[s], &tmB, s * BK, tile_n, mb_full[s]);
            }
        }
        for (int kc = 0; kc < NC; kc++) {
            const int b = kc % STAGES;
            mbar_wait(mb_full[b], phf[b]); phf[b] ^= 1;
            #pragma unroll
            for (int s2 = 0; s2 < 4; s2++) {   // BK=32 floats = 4 x (K=8) tf32 MMAs
                const uint32_t en = (kc > 0 || s2 > 0) ? 1u : 0u;
                mma_tf32_ss(tmem,       ad0[b] + 2 * s2, bd[b] + 2 * s2, IDESC_TF32, en);
                mma_tf32_ss(tmem + 256, ad1[b] + 2 * s2, bd[b] + 2 * s2, IDESC_TF32, en);
            }
            tc_commit(mb_done[b]);
            if (kc + STAGES < NC) {
                mbar_wait(mb_done[b], phd[b]); phd[b] ^= 1;
                mbar_expect_tx(mb_full[b], CHUNK_BYTES);
                tma_2d(bufA[b], &tmA, (kc + STAGES) * BK, tile_m, mb_full[b]);
                tma_2d(bufB[b], &tmB, (kc + STAGES) * BK, tile_n, mb_full[b]);
            }
        }
        const int bl = (NC - 1) % STAGES;
        mbar_wait(mb_done[bl], phd[bl]);
    }
    __syncthreads();
    TC_FENCE_AFTER();

    // epilogue: 8 warps. half = warp>>2 selects TMEM col half + M half.
    const int half = warp >> 2;
    const int row  = tile_m + half * 128 + (warp & 3) * 32 + lane;
    const uint32_t dbase = tmem + half * 256;
    #pragma unroll 1
    for (int cc = 0; cc < 8; cc++) {
        uint32_t r[32];
        TC_LD_X32(r, dbase + cc * 32);
        TC_WAIT_LD();
        const int colbase = tile_n + cc * 32;
        float4* dst = reinterpret_cast<float4*>(&C[(size_t)row * N + colbase]);
        #pragma unroll
        for (int j = 0; j < 32; j += 4) {
            float4 v;
            v.x = __uint_as_float(r[j + 0]);
            v.y = __uint_as_float(r[j + 1]);
            v.z = __uint_as_float(r[j + 2]);
            v.w = __uint_as_float(r[j + 3]);
            if (EPI >= 1) {
                v.x += bias[colbase + j + 0]; v.y += bias[colbase + j + 1];
                v.z += bias[colbase + j + 2]; v.w += bias[colbase + j + 3];
            }
            if (EPI == 1) {
                v.x = to_tf32(fmaxf(v.x, 0.f)); v.y = to_tf32(fmaxf(v.y, 0.f));
                v.z = to_tf32(fmaxf(v.z, 0.f)); v.w = to_tf32(fmaxf(v.w, 0.f));
            }
            if (EPI == 2) {
                float4 rv = *reinterpret_cast<const float4*>(&res[(size_t)row * N + colbase + j]);
                v.x += rv.x; v.y += rv.y; v.z += rv.z; v.w += rv.w;
            }
            dst[j / 4] = v;
        }
    }
    __syncthreads();
    if (warp == 0) TC_DEALLOC(tmem, 512);
#endif
}

// ================= transpose (+pad rows, +tf32 round) =================
__global__ void transpose_rn_kernel(const float* __restrict__ in, float* __restrict__ out,
                                    int R, int Cc, int Cp) {
    __shared__ float tile[32][33];
    const int c0 = blockIdx.x * 32, r0 = blockIdx.y * 32;
    const int x = c0 + threadIdx.x;
    #pragma unroll
    for (int i = 0; i < 32; i += 8) {
        const int y = r0 + threadIdx.y + i;
        float v = 0.f;
        if (x < Cc && y < R) v = in[(size_t)y * Cc + x];
        tile[threadIdx.y + i][threadIdx.x] = v;
    }
    __syncthreads();
    const int ox = r0 + threadIdx.x;
    #pragma unroll
    for (int i = 0; i < 32; i += 8) {
        const int oy = c0 + threadIdx.y + i;
        if (oy < Cp && ox < R)
            out[(size_t)oy * R + ox] = to_tf32(tile[threadIdx.x][threadIdx.y + i]);
    }
}

// ================= t-tiled softmax + causal dynamic conv + LayerNorm =================
// block = (32 timesteps) x (full C) x (one b). x tile staged in smem once.
__global__ __launch_bounds__(512)
void dynconv_ln_kernel(const float* __restrict__ x, const float* __restrict__ wraw,
                       const float* __restrict__ b_lin,
                       const float* __restrict__ ln_g, const float* __restrict__ ln_b,
                       float* __restrict__ y, float* __restrict__ yrn) {
    extern __shared__ float sm[];
    float* xs  = sm;                                  // [46][1024]
    float* ws  = xs + XS_ROWS * C_DIM;                // [32][240]
    float* red = ws + TT * (H_DIM * K_TAPS);          // [32] sums + [32..33] stats

    const int t0  = blockIdx.x * TT;
    const int b   = blockIdx.y;
    const int tid = threadIdx.x;

    // stage x tile: rows r=0..45 map to t = t0-14+r (zeros for t<0)
    {
        float4* xs4 = reinterpret_cast<float4*>(xs);
        const int total4 = XS_ROWS * (C_DIM / 4);
        for (int i = tid; i < total4; i += 512) {
            const int r = i / (C_DIM / 4);
            const int cc = i % (C_DIM / 4);
            const int t = t0 - HALO + r;
            float4 v = make_float4(0.f, 0.f, 0.f, 0.f);
            if (t >= 0)
                v = reinterpret_cast<const float4*>(x)[((size_t)(t * B_DIM + b)) * (C_DIM / 4) + cc];
            xs4[i] = v;
        }
    }
    // stage conv logits (+bias)
    for (int i = tid; i < TT * (H_DIM * K_TAPS); i += 512) {
        const int lt = i / (H_DIM * K_TAPS);
        const int j  = i % (H_DIM * K_TAPS);
        ws[i] = wraw[(size_t)((t0 + lt) * B_DIM + b) * NPAD + j] + b_lin[j];
    }
    __syncthreads();

    // softmax: 32 rows x 16 heads = 512 tasks, one per thread
    {
        const int lt = tid >> 4;
        const int hd = tid & 15;
        float* p = ws + lt * (H_DIM * K_TAPS) + hd * K_TAPS;
        float mx = -1e30f;
        #pragma unroll
        for (int k = 0; k < K_TAPS; k++) mx = fmaxf(mx, p[k]);
        float e[K_TAPS]; float s = 0.f;
        #pragma unroll
        for (int k = 0; k < K_TAPS; k++) { e[k] = expf(p[k] - mx); s += e[k]; }
        const float inv = 1.0f / s;
        #pragma unroll
        for (int k = 0; k < K_TAPS; k++) p[k] = e[k] * inv;
    }
    __syncthreads();

    // per-thread channels (fixed): c0 = 2*tid, c0+1 (same head: 64 ch/head)
    const int c0 = tid * 2;
    const int h  = c0 >> 6;
    const float g0 = ln_g[c0], g1 = ln_g[c0 + 1];
    const float bb0 = ln_b[c0], bb1 = ln_b[c0 + 1];
    const int wid = tid >> 5, lane = tid & 31;

    for (int lt = 0; lt < TT; lt++) {
        const float* wrow = ws + lt * (H_DIM * K_TAPS) + h * K_TAPS;
        float a0 = 0.f, a1 = 0.f;
        #pragma unroll
        for (int k = 0; k < K_TAPS; k++) {
            const float wgt = wrow[k];
            const float2 xv = *reinterpret_cast<const float2*>(&xs[(lt + k) * C_DIM + c0]);
            a0 += wgt * xv.x;
            a1 += wgt * xv.y;
        }
        float s1 = a0 + a1;
        float s2 = a0 * a0 + a1 * a1;
        #pragma unroll
        for (int off = 16; off > 0; off >>= 1) {
            s1 += __shfl_down_sync(0xFFFFFFFFu, s1, off);
            s2 += __shfl_down_sync(0xFFFFFFFFu, s2, off);
        }
        if (lane == 0) { red[wid] = s1; red[16 + wid] = s2; }
        __syncthreads();
        if (tid == 0) {
            float sa = 0.f, sb = 0.f;
            #pragma unroll
            for (int i = 0; i < 16; i++) { sa += red[i]; sb += red[16 + i]; }
            const float mu = sa * (1.0f / C_DIM);
            const float var = sb * (1.0f / C_DIM) - mu * mu;
            red[32] = mu;
            red[33] = rsqrtf(var + LN_EPS);
        }
        __syncthreads();
        const float mu = red[32], rstd = red[33];
        const float v0 = (a0 - mu) * rstd * g0 + bb0;
        const float v1 = (a1 - mu) * rstd * g1 + bb1;
        const size_t base = (size_t)((t0 + lt) * B_DIM + b) * C_DIM + c0;
        *reinterpret_cast<float2*>(&y[base])   = make_float2(v0, v1);
        *reinterpret_cast<float2*>(&yrn[base]) = make_float2(to_tf32(v0), to_tf32(v1));
    }
}

// ================= host side =================
typedef CUresult (*PFN_encodeTiled)(CUtensorMap*, CUtensorMapDataType, cuuint32_t, void*,
                                    const cuuint64_t*, const cuuint64_t*, const cuuint32_t*,
                                    const cuuint32_t*, CUtensorMapInterleave, CUtensorMapSwizzle,
                                    CUtensorMapL2promotion, CUtensorMapFloatOOBfill);

static PFN_encodeTiled get_encoder() {
    static PFN_encodeTiled fn = nullptr;
    if (!fn) {
        void* h = dlopen("libcuda.so.1", RTLD_LAZY | RTLD_GLOBAL);
        if (!h) h = dlopen("libcuda.so", RTLD_LAZY | RTLD_GLOBAL);
        if (h) fn = (PFN_encodeTiled)dlsym(h, "cuTensorMapEncodeTiled");
    }
    return fn;
}

static void make_map(CUtensorMap* m, const void* ptr, uint64_t d0, uint64_t d1,
                     uint32_t b0, uint32_t b1) {
    cuuint64_t dims[2] = { d0, d1 };
    cuuint64_t strides[1] = { d0 * 4 };
    cuuint32_t box[2] = { b0, b1 };
    cuuint32_t es[2] = { 1, 1 };
    PFN_encodeTiled enc = get_encoder();
    if (enc)
        enc(m, CU_TENSOR_MAP_DATA_TYPE_FLOAT32, 2, (void*)ptr, dims, strides, box, es,
            CU_TENSOR_MAP_INTERLEAVE_NONE, CU_TENSOR_MAP_SWIZZLE_128B,
            CU_TENSOR_MAP_L2_PROMOTION_L2_128B, CU_TENSOR_MAP_FLOAT_OOB_FILL_NONE);
}

extern "C" void kernel_launch(void* const* d_in, const int* in_sizes, int n_in,
                              void* d_out, int out_size) {
    const float* x     = (const float*)d_in[0];
    const float* w_lin = (const float*)d_in[1];
    const float* b_lin = (const float*)d_in[2];
    const float* ln_g  = (const float*)d_in[3];
    const float* ln_b  = (const float*)d_in[4];
    const float* fc1_w = (const float*)d_in[5];
    const float* fc1_b = (const float*)d_in[6];
    const float* fc2_w = (const float*)d_in[7];
    const float* fc2_b = (const float*)d_in[8];
    float* out = (float*)d_out;

    float *wlinT, *fc1wT, *fc2wT, *wraw, *y, *yrn, *h;
    cudaGetSymbolAddress((void**)&wlinT, g_wlinT);
    cudaGetSymbolAddress((void**)&fc1wT, g_fc1wT);
    cudaGetSymbolAddress((void**)&fc2wT, g_fc2wT);
    cudaGetSymbolAddress((void**)&wraw, g_wraw);
    cudaGetSymbolAddress((void**)&y, g_y);
    cudaGetSymbolAddress((void**)&yrn, g_yrn);
    cudaGetSymbolAddress((void**)&h, g_h);

    cudaFuncSetAttribute(tc_gemm<0>, cudaFuncAttributeMaxDynamicSharedMemorySize, SMEM_BYTES);
    cudaFuncSetAttribute(tc_gemm<1>, cudaFuncAttributeMaxDynamicSharedMemorySize, SMEM_BYTES);
    cudaFuncSetAttribute(tc_gemm<2>, cudaFuncAttributeMaxDynamicSharedMemorySize, SMEM_BYTES);
    cudaFuncSetAttribute(dynconv_ln_kernel, cudaFuncAttributeMaxDynamicSharedMemorySize, DC_SMEM);

    CUtensorMap mA1{}, mB1{}, mA2{}, mB2{}, mA3{}, mB3{};
    make_map(&mA1, x,     C_DIM, M_DIM, BK, 256);
    make_map(&mB1, wlinT, C_DIM, NPAD,  BK, 256);
    make_map(&mA2, yrn,   C_DIM, M_DIM, BK, 256);
    make_map(&mB2, fc1wT, C_DIM, F_DIM, BK, 256);
    make_map(&mA3, h,     F_DIM, M_DIM, BK, 256);
    make_map(&mB3, fc2wT, F_DIM, C_DIM, BK, 256);

    dim3 tb(32, 8);
    // 1) transposed tf32-rounded weights
    transpose_rn_kernel<<<dim3(NPAD / 32, C_DIM / 32), tb>>>(w_lin, wlinT, C_DIM, H_DIM * K_TAPS, NPAD);
    transpose_rn_kernel<<<dim3(F_DIM / 32, C_DIM / 32), tb>>>(fc1_w, fc1wT, C_DIM, F_DIM, F_DIM);
    transpose_rn_kernel<<<dim3(C_DIM / 32, F_DIM / 32), tb>>>(fc2_w, fc2wT, F_DIM, C_DIM, C_DIM);

    // 2) conv-weight projection: wraw = x @ w_lin (N padded to 256)
    tc_gemm<0><<<dim3(NPAD / BN, M_DIM / BM), 256, SMEM_BYTES>>>(
        mA1, mB1, nullptr, nullptr, wraw, NPAD, C_DIM / BK);

    // 3) softmax + causal conv + LayerNorm (t-tiled, x staged in smem)
    dynconv_ln_kernel<<<dim3(T_DIM / TT, B_DIM), 512, DC_SMEM>>>(
        x, wraw, b_lin, ln_g, ln_b, y, yrn);

    // 4) fc1 + ReLU
    tc_gemm<1><<<dim3(F_DIM / BN, M_DIM / BM), 256, SMEM_BYTES>>>(
        mA2, mB2, fc1_b, nullptr, h, F_DIM, C_DIM / BK);

    // 5) fc2 + bias + residual
    tc_gemm<2><<<dim3(C_DIM / BN, M_DIM / BM), 256, SMEM_BYTES>>>(
        mA3, mB3, fc2_b, y, out, C_DIM, F_DIM / BK);
}

// round 5
// speedup vs baseline: 1.1270x; 1.1270x over previous
#include <cuda_runtime.h>
#include <cuda.h>
#include <dlfcn.h>
#include <math.h>
#include <stdint.h>

// ---------------- problem constants ----------------
#define T_DIM 1024
#define B_DIM 8
#define C_DIM 1024
#define F_DIM 4096
#define H_DIM 16
#define K_TAPS 15
#define M_DIM (T_DIM * B_DIM)   // 8192
#define NPAD 256
#define LN_EPS 1e-5f

// tcgen05 GEMM tile config
#define BN 256
#define BK 32                            // floats per k-chunk (128 bytes)
#define STAGES 3

// dynconv tiling
#define TT 32
#define HALO (K_TAPS - 1)
#define XS_ROWS (TT + HALO)              // 46
#define DC_SMEM ((XS_ROWS * C_DIM + TT * (H_DIM * K_TAPS) + 64) * 4)

// arch-specific feature gate (tcgen05 only on the sm_103a pass)
#if defined(__CUDA_ARCH_FEAT_SM103_ALL) || defined(__CUDA_ARCH_FEAT_SM100_ALL) || \
    (defined(__CUDA_ARCH_SPECIFIC__) && (__CUDA_ARCH_SPECIFIC__ >= 1000)) ||      \
    (defined(__CUDA_ARCH_FAMILY_SPECIFIC__) && (__CUDA_ARCH_FAMILY_SPECIFIC__ >= 1000))
#define TC_OK 1
#else
#define TC_OK 0
#endif

// ---------------- scratch (device globals) ----------------
__device__ float g_wlinT[NPAD * C_DIM];
__device__ float g_fc1wT[(size_t)F_DIM * C_DIM];
__device__ float g_fc2wT[(size_t)C_DIM * F_DIM];
__device__ float g_wraw[(size_t)M_DIM * NPAD];
__device__ float g_y[(size_t)M_DIM * C_DIM];
__device__ float g_yrn[(size_t)M_DIM * C_DIM];
__device__ float g_h[(size_t)M_DIM * F_DIM];

// ---------------- helpers ----------------
__device__ __forceinline__ float to_tf32(float x) {
    float r;
    asm("cvt.rna.tf32.f32 %0, %1;" : "=f"(r) : "f"(x));
    return r;
}
__device__ __forceinline__ uint32_t smem_u32(const void* p) {
    uint32_t a;
    asm("{ .reg .u64 t; cvta.to.shared.u64 t, %1; cvt.u32.u64 %0, t; }" : "=r"(a) : "l"(p));
    return a;
}
__device__ __forceinline__ uint32_t elect_one() {
    uint32_t p;
    asm volatile("{ .reg .pred p; elect.sync _|p, 0xFFFFFFFF; selp.b32 %0, 1, 0, p; }" : "=r"(p));
    return p;
}
__device__ __forceinline__ void mbar_init(uint32_t a, uint32_t cnt) {
    asm volatile("mbarrier.init.shared.b64 [%0], %1;" :: "r"(a), "r"(cnt) : "memory");
}
__device__ __forceinline__ void mbar_expect_tx(uint32_t a, uint32_t bytes) {
    asm volatile("mbarrier.arrive.expect_tx.shared.b64 _, [%0], %1;" :: "r"(a), "r"(bytes) : "memory");
}
__device__ __forceinline__ void mbar_wait(uint32_t a, uint32_t parity) {
    uint32_t done;
    asm volatile(
        "{ .reg .pred p;\n\t"
        "mbarrier.try_wait.parity.acquire.cta.shared::cta.b64 p, [%1], %2;\n\t"
        "selp.b32 %0, 1, 0, p; }" : "=r"(done) : "r"(a), "r"(parity) : "memory");
    if (!done) {
        asm volatile(
            "{ .reg .pred P1;\n\t"
            "WL_%=:\n\t"
            "mbarrier.try_wait.parity.acquire.cta.shared::cta.b64 P1, [%0], %1, 0x989680;\n\t"
            "@P1 bra.uni WD_%=;\n\t"
            "bra.uni WL_%=;\n\t"
            "WD_%=: }" :: "r"(a), "r"(parity) : "memory");
    }
}
#if TC_OK
__device__ __forceinline__ void tma_2d(uint32_t dst, const void* map, int cx, int cy, uint32_t mbar) {
    asm volatile(
        "cp.async.bulk.tensor.2d.shared::cta.global.tile.mbarrier::complete_tx::bytes "
        "[%0], [%1, {%2, %3}], [%4];"
        :: "r"(dst), "l"(map), "r"(cx), "r"(cy), "r"(mbar) : "memory");
}
__device__ __forceinline__ void mma_tf32_ss(uint32_t d, uint64_t adesc, uint64_t bdesc,
                                            uint32_t idesc, uint32_t en) {
    asm volatile(
        "{ .reg .pred p;\n\t"
        "setp.ne.u32 p, %4, 0;\n\t"
        "tcgen05.mma.cta_group::1.kind::tf32 [%0], %1, %2, %3, p; }"
        :: "r"(d), "l"(adesc), "l"(bdesc), "r"(idesc), "r"(en) : "memory");
}
__device__ __forceinline__ void tc_commit(uint32_t mbar) {
    asm volatile(
        "tcgen05.commit.cta_group::1.mbarrier::arrive::one.shared::cluster.b64 [%0];"
        :: "r"(mbar) : "memory");
}
#define TC_ALLOC(smem_addr, ncols) \
    asm volatile("tcgen05.alloc.cta_group::1.sync.aligned.shared::cta.b32 [%0], %1;" \
                 :: "r"(smem_addr), "r"(ncols) : "memory")
#define TC_RELINQ() \
    asm volatile("tcgen05.relinquish_alloc_permit.cta_group::1.sync.aligned;")
#define TC_DEALLOC(tmem, ncols) \
    asm volatile("tcgen05.dealloc.cta_group::1.sync.aligned.b32 %0, %1;" :: "r"(tmem), "r"(ncols))
#define TC_FENCE_AFTER()  asm volatile("tcgen05.fence::after_thread_sync;" ::: "memory")
#define TC_WAIT_LD()      asm volatile("tcgen05.wait::ld.sync.aligned;" ::: "memory")
#define TC_LD_X32(r, addr) \
    asm volatile("tcgen05.ld.sync.aligned.32x32b.x32.b32 " \
        "{%0, %1, %2, %3, %4, %5, %6, %7, %8, %9, %10, %11, %12, %13, %14, %15, " \
        " %16, %17, %18, %19, %20, %21, %22, %23, %24, %25, %26, %27, %28, %29, %30, %31}, [%32];" \
        : "=r"((r)[0]), "=r"((r)[1]), "=r"((r)[2]), "=r"((r)[3]), \
          "=r"((r)[4]), "=r"((r)[5]), "=r"((r)[6]), "=r"((r)[7]), \
          "=r"((r)[8]), "=r"((r)[9]), "=r"((r)[10]), "=r"((r)[11]), \
          "=r"((r)[12]), "=r"((r)[13]), "=r"((r)[14]), "=r"((r)[15]), \
          "=r"((r)[16]), "=r"((r)[17]), "=r"((r)[18]), "=r"((r)[19]), \
          "=r"((r)[20]), "=r"((r)[21]), "=r"((r)[22]), "=r"((r)[23]), \
          "=r"((r)[24]), "=r"((r)[25]), "=r"((r)[26]), "=r"((r)[27]), \
          "=r"((r)[28]), "=r"((r)[29]), "=r"((r)[30]), "=r"((r)[31]) \
        : "r"(addr))

__device__ __forceinline__ uint64_t smem_desc_sw128(uint32_t addr) {
    return ((uint64_t)2 << 61) | ((uint64_t)1 << 46) | ((uint64_t)64 << 32) |
           ((uint64_t)1 << 16) | (((uint64_t)addr >> 4) & 0x3FFF);
}
#define IDESC_TF32 ((1u << 4) | (2u << 7) | (2u << 10) | ((BN / 8) << 17) | ((128 / 16) << 24))
#endif  // TC_OK

// ================= tcgen05 tf32 GEMM =================
// Tile: (128*MH) x 256. MH MMAs per K-step into TMEM halves. 3-stage TMA pipe.
// Pipeline: MMAs issued BEFORE the deferred done-wait of the previous k-chunk,
// so the tensor queue never drains while the producer refills smem.
// EPI: 0 plain, 1 bias+relu+tf32-round, 2 bias+residual
template <int EPI, int MH>
__global__ __launch_bounds__(256)
void tc_gemm(const __grid_constant__ CUtensorMap tmA,
             const __grid_constant__ CUtensorMap tmB,
             const float* __restrict__ bias, const float* __restrict__ res,
             float* __restrict__ C, int N, int NC) {
#if TC_OK
    constexpr int BMk = 128 * MH;
    constexpr int CA = BMk * BK * 4;
    constexpr int CB = BN * BK * 4;
    constexpr int CBYTES = CA + CB;
    constexpr int TCOLS = 256 * MH;

    extern __shared__ __align__(1024) char smem[];
    const int tid  = threadIdx.x;
    const int warp = tid >> 5;
    const int lane = tid & 31;

    uint32_t sb = (smem_u32(smem) + 1023u) & ~1023u;
    const uint32_t tmem_ptr_addr = sb;
    uint32_t mb_full[STAGES], mb_done[STAGES], bufA[STAGES], bufB[STAGES];
    #pragma unroll
    for (int s = 0; s < STAGES; s++) {
        mb_full[s] = sb + 8 + 8 * s;
        mb_done[s] = sb + 8 + 8 * STAGES + 8 * s;
        bufA[s] = sb + 1024 + s * CBYTES;
        bufB[s] = bufA[s] + CA;
    }

    if (warp == 0) {
        TC_ALLOC(tmem_ptr_addr, TCOLS);
        TC_RELINQ();
    }
    if (tid == 0) {
        #pragma unroll
        for (int s = 0; s < STAGES; s++) { mbar_init(mb_full[s], 1); mbar_init(mb_done[s], 1); }
    }
    __syncthreads();

    uint32_t tmem;
    asm volatile("ld.shared.b32 %0, [%1];" : "=r"(tmem) : "r"(tmem_ptr_addr));

    const int tile_m = blockIdx.y * BMk;
    const int tile_n = blockIdx.x * BN;

    if (warp == 0 && elect_one()) {
        uint64_t ad[STAGES][MH], bd[STAGES];
        int phf[STAGES], phd[STAGES];
        #pragma unroll
        for (int s = 0; s < STAGES; s++) {
            #pragma unroll
            for (int hh = 0; hh < MH; hh++)
                ad[s][hh] = smem_desc_sw128(bufA[s] + hh * 128 * 128);
            bd[s] = smem_desc_sw128(bufB[s]);
            phf[s] = 0; phd[s] = 0;
        }
        // prologue: fill all stages
        #pragma unroll
        for (int s = 0; s < STAGES; s++) {
            mbar_expect_tx(mb_full[s], CBYTES);
            tma_2d(bufA[s], &tmA, s * BK, tile_m, mb_full[s]);
            tma_2d(bufB[s], &tmB, s * BK, tile_n, mb_full[s]);
        }
        for (int kc = 0; kc < NC; kc++) {
            const int b = kc % STAGES;
            mbar_wait(mb_full[b], phf[b]); phf[b] ^= 1;
            #pragma unroll
            for (int s2 = 0; s2 < 4; s2++) {            // BK=32 = 4 x (K=8) tf32 MMAs
                const uint32_t en = (kc > 0 || s2 > 0) ? 1u : 0u;
                #pragma unroll
                for (int hh = 0; hh < MH; hh++)
                    mma_tf32_ss(tmem + hh * 256, ad[b][hh] + 2 * s2, bd[b] + 2 * s2,
                                IDESC_TF32, en);
            }
            tc_commit(mb_done[b]);
            // deferred refill: stage consumed at kc-1 gets chunk kc-1+STAGES.
            // While we block on done[bp], the tensor pipe executes kc's queued MMAs.
            const int j = kc - 1 + STAGES;
            if (kc >= 1 && j < NC) {
                const int bp = (kc - 1) % STAGES;
                mbar_wait(mb_done[bp], phd[bp]); phd[bp] ^= 1;
                mbar_expect_tx(mb_full[bp], CBYTES);
                tma_2d(bufA[bp], &tmA, j * BK, tile_m, mb_full[bp]);
                tma_2d(bufB[bp], &tmB, j * BK, tile_n, mb_full[bp]);
            }
        }
        const int bl = (NC - 1) % STAGES;
        mbar_wait(mb_done[bl], phd[bl]);   // last commit done => all MMAs done (in-order)
    }
    __syncthreads();
    TC_FENCE_AFTER();

    // epilogue: 8 warps; half = warp>>2
    const int half = warp >> 2;
    uint32_t dbase;
    int row, col0, nchunk;
    if (MH == 2) {
        dbase = tmem + half * 256;
        row = tile_m + half * 128 + (warp & 3) * 32 + lane;
        col0 = tile_n;
        nchunk = 8;
    } else {
        dbase = tmem + half * 128;
        row = tile_m + (warp & 3) * 32 + lane;
        col0 = tile_n + half * 128;
        nchunk = 4;
    }
    #pragma unroll 1
    for (int cc = 0; cc < nchunk; cc++) {
        uint32_t r[32];
        TC_LD_X32(r, dbase + cc * 32);
        TC_WAIT_LD();
        const int colbase = col0 + cc * 32;
        float4* dst = reinterpret_cast<float4*>(&C[(size_t)row * N + colbase]);
        #pragma unroll
        for (int j = 0; j < 32; j += 4) {
            float4 v;
            v.x = __uint_as_float(r[j + 0]);
            v.y = __uint_as_float(r[j + 1]);
            v.z = __uint_as_float(r[j + 2]);
            v.w = __uint_as_float(r[j + 3]);
            if (EPI >= 1) {
                v.x += bias[colbase + j + 0]; v.y += bias[colbase + j + 1];
                v.z += bias[colbase + j + 2]; v.w += bias[colbase + j + 3];
            }
            if (EPI == 1) {
                v.x = to_tf32(fmaxf(v.x, 0.f)); v.y = to_tf32(fmaxf(v.y, 0.f));
                v.z = to_tf32(fmaxf(v.z, 0.f)); v.w = to_tf32(fmaxf(v.w, 0.f));
            }
            if (EPI == 2) {
                float4 rv = *reinterpret_cast<const float4*>(&res[(size_t)row * N + colbase + j]);
                v.x += rv.x; v.y += rv.y; v.z += rv.z; v.w += rv.w;
            }
            dst[j / 4] = v;
        }
    }
    __syncthreads();
    if (warp == 0) TC_DEALLOC(tmem, TCOLS);
#endif
}

// ================= transpose (+pad rows, +tf32 round) =================
__global__ void transpose_rn_kernel(const float* __restrict__ in, float* __restrict__ out,
                                    int R, int Cc, int Cp) {
    __shared__ float tile[32][33];
    const int c0 = blockIdx.x * 32, r0 = blockIdx.y * 32;
    const int x = c0 + threadIdx.x;
    #pragma unroll
    for (int i = 0; i < 32; i += 8) {
        const int y = r0 + threadIdx.y + i;
        float v = 0.f;
        if (x < Cc && y < R) v = in[(size_t)y * Cc + x];
        tile[threadIdx.y + i][threadIdx.x] = v;
    }
    __syncthreads();
    const int ox = r0 + threadIdx.x;
    #pragma unroll
    for (int i = 0; i < 32; i += 8) {
        const int oy = c0 + threadIdx.y + i;
        if (oy < Cp && ox < R)
            out[(size_t)oy * R + ox] = to_tf32(tile[threadIdx.x][threadIdx.y + i]);
    }
}

// ================= t-tiled softmax + causal dynamic conv + LayerNorm =================
__global__ __launch_bounds__(512)
void dynconv_ln_kernel(const float* __restrict__ x, const float* __restrict__ wraw,
                       const float* __restrict__ b_lin,
                       const float* __restrict__ ln_g, const float* __restrict__ ln_b,
                       float* __restrict__ y, float* __restrict__ yrn) {
    extern __shared__ float sm[];
    float* xs  = sm;                                  // [46][1024]
    float* ws  = xs + XS_ROWS * C_DIM;                // [32][240]
    float* red = ws + TT * (H_DIM * K_TAPS);          // [32] + stats

    const int t0  = blockIdx.x * TT;
    const int b   = blockIdx.y;
    const int tid = threadIdx.x;

    {
        float4* xs4 = reinterpret_cast<float4*>(xs);
        const int total4 = XS_ROWS * (C_DIM / 4);
        for (int i = tid; i < total4; i += 512) {
            const int r = i / (C_DIM / 4);
            const int cc = i % (C_DIM / 4);
            const int t = t0 - HALO + r;
            float4 v = make_float4(0.f, 0.f, 0.f, 0.f);
            if (t >= 0)
                v = reinterpret_cast<const float4*>(x)[((size_t)(t * B_DIM + b)) * (C_DIM / 4) + cc];
            xs4[i] = v;
        }
    }
    for (int i = tid; i < TT * (H_DIM * K_TAPS); i += 512) {
        const int lt = i / (H_DIM * K_TAPS);
        const int j  = i % (H_DIM * K_TAPS);
        ws[i] = wraw[(size_t)((t0 + lt) * B_DIM + b) * NPAD + j] + b_lin[j];
    }
    __syncthreads();

    {
        const int lt = tid >> 4;
        const int hd = tid & 15;
        float* p = ws + lt * (H_DIM * K_TAPS) + hd * K_TAPS;
        float mx = -1e30f;
        #pragma unroll
        for (int k = 0; k < K_TAPS; k++) mx = fmaxf(mx, p[k]);
        float e[K_TAPS]; float s = 0.f;
        #pragma unroll
        for (int k = 0; k < K_TAPS; k++) { e[k] = expf(p[k] - mx); s += e[k]; }
        const float inv = 1.0f / s;
        #pragma unroll
        for (int k = 0; k < K_TAPS; k++) p[k] = e[k] * inv;
    }
    __syncthreads();

    const int c0 = tid * 2;
    const int h  = c0 >> 6;
    const float g0 = ln_g[c0], g1 = ln_g[c0 + 1];
    const float bb0 = ln_b[c0], bb1 = ln_b[c0 + 1];
    const int wid = tid >> 5, lane = tid & 31;

    for (int lt = 0; lt < TT; lt++) {
        const float* wrow = ws + lt * (H_DIM * K_TAPS) + h * K_TAPS;
        float a0 = 0.f, a1 = 0.f;
        #pragma unroll
        for (int k = 0; k < K_TAPS; k++) {
            const float wgt = wrow[k];
            const float2 xv = *reinterpret_cast<const float2*>(&xs[(lt + k) * C_DIM + c0]);
            a0 += wgt * xv.x;
            a1 += wgt * xv.y;
        }
        float s1 = a0 + a1;
        float s2 = a0 * a0 + a1 * a1;
        #pragma unroll
        for (int off = 16; off > 0; off >>= 1) {
            s1 += __shfl_down_sync(0xFFFFFFFFu, s1, off);
            s2 += __shfl_down_sync(0xFFFFFFFFu, s2, off);
        }
        if (lane == 0) { red[wid] = s1; red[16 + wid] = s2; }
        __syncthreads();
        if (tid == 0) {
            float sa = 0.f, sb2 = 0.f;
            #pragma unroll
            for (int i = 0; i < 16; i++) { sa += red[i]; sb2 += red[16 + i]; }
            const float mu = sa * (1.0f / C_DIM);
            const float var = sb2 * (1.0f / C_DIM) - mu * mu;
            red[32] = mu;
            red[33] = rsqrtf(var + LN_EPS);
        }
        __syncthreads();
        const float mu = red[32], rstd = red[33];
        const float v0 = (a0 - mu) * rstd * g0 + bb0;
        const float v1 = (a1 - mu) * rstd * g1 + bb1;
        const size_t base = (size_t)((t0 + lt) * B_DIM + b) * C_DIM + c0;
        *reinterpret_cast<float2*>(&y[base])   = make_float2(v0, v1);
        *reinterpret_cast<float2*>(&yrn[base]) = make_float2(to_tf32(v0), to_tf32(v1));
    }
}

// ================= host side =================
typedef CUresult (*PFN_encodeTiled)(CUtensorMap*, CUtensorMapDataType, cuuint32_t, void*,
                                    const cuuint64_t*, const cuuint64_t*, const cuuint32_t*,
                                    const cuuint32_t*, CUtensorMapInterleave, CUtensorMapSwizzle,
                                    CUtensorMapL2promotion, CUtensorMapFloatOOBfill);

static PFN_encodeTiled get_encoder() {
    static PFN_encodeTiled fn = nullptr;
    if (!fn) {
        void* h = dlopen("libcuda.so.1", RTLD_LAZY | RTLD_GLOBAL);
        if (!h) h = dlopen("libcuda.so", RTLD_LAZY | RTLD_GLOBAL);
        if (h) fn = (PFN_encodeTiled)dlsym(h, "cuTensorMapEncodeTiled");
    }
    return fn;
}

static void make_map(CUtensorMap* m, const void* ptr, uint64_t d0, uint64_t d1,
                     uint32_t b0, uint32_t b1) {
    cuuint64_t dims[2] = { d0, d1 };
    cuuint64_t strides[1] = { d0 * 4 };
    cuuint32_t box[2] = { b0, b1 };
    cuuint32_t es[2] = { 1, 1 };
    PFN_encodeTiled enc = get_encoder();
    if (enc)
        enc(m, CU_TENSOR_MAP_DATA_TYPE_FLOAT32, 2, (void*)ptr, dims, strides, box, es,
            CU_TENSOR_MAP_INTERLEAVE_NONE, CU_TENSOR_MAP_SWIZZLE_128B,
            CU_TENSOR_MAP_L2_PROMOTION_L2_128B, CU_TENSOR_MAP_FLOAT_OOB_FILL_NONE);
}

extern "C" void kernel_launch(void* const* d_in, const int* in_sizes, int n_in,
                              void* d_out, int out_size) {
    const float* x     = (const float*)d_in[0];
    const float* w_lin = (const float*)d_in[1];
    const float* b_lin = (const float*)d_in[2];
    const float* ln_g  = (const float*)d_in[3];
    const float* ln_b  = (const float*)d_in[4];
    const float* fc1_w = (const float*)d_in[5];
    const float* fc1_b = (const float*)d_in[6];
    const float* fc2_w = (const float*)d_in[7];
    const float* fc2_b = (const float*)d_in[8];
    float* out = (float*)d_out;

    float *wlinT, *fc1wT, *fc2wT, *wraw, *y, *yrn, *h;
    cudaGetSymbolAddress((void**)&wlinT, g_wlinT);
    cudaGetSymbolAddress((void**)&fc1wT, g_fc1wT);
    cudaGetSymbolAddress((void**)&fc2wT, g_fc2wT);
    cudaGetSymbolAddress((void**)&wraw, g_wraw);
    cudaGetSymbolAddress((void**)&y, g_y);
    cudaGetSymbolAddress((void**)&yrn, g_yrn);
    cudaGetSymbolAddress((void**)&h, g_h);

    const int smem1 = 1024 + STAGES * ((128 * BK + BN * BK) * 4);   // MH=1
    const int smem2 = 1024 + STAGES * ((256 * BK + BN * BK) * 4);   // MH=2
    cudaFuncSetAttribute((const void*)tc_gemm<0, 1>, cudaFuncAttributeMaxDynamicSharedMemorySize, smem1);
    cudaFuncSetAttribute((const void*)tc_gemm<1, 2>, cudaFuncAttributeMaxDynamicSharedMemorySize, smem2);
    cudaFuncSetAttribute((const void*)tc_gemm<2, 2>, cudaFuncAttributeMaxDynamicSharedMemorySize, smem2);
    cudaFuncSetAttribute((const void*)dynconv_ln_kernel, cudaFuncAttributeMaxDynamicSharedMemorySize, DC_SMEM);

    CUtensorMap mA1{}, mB1{}, mA2{}, mB2{}, mA3{}, mB3{};
    make_map(&mA1, x,     C_DIM, M_DIM, BK, 128);
    make_map(&mB1, wlinT, C_DIM, NPAD,  BK, 256);
    make_map(&mA2, yrn,   C_DIM, M_DIM, BK, 256);
    make_map(&mB2, fc1wT, C_DIM, F_DIM, BK, 256);
    make_map(&mA3, h,     F_DIM, M_DIM, BK, 256);
    make_map(&mB3, fc2wT, F_DIM, C_DIM, BK, 256);

    dim3 tb(32, 8);
    transpose_rn_kernel<<<dim3(NPAD / 32, C_DIM / 32), tb>>>(w_lin, wlinT, C_DIM, H_DIM * K_TAPS, NPAD);
    transpose_rn_kernel<<<dim3(F_DIM / 32, C_DIM / 32), tb>>>(fc1_w, fc1wT, C_DIM, F_DIM, F_DIM);
    transpose_rn_kernel<<<dim3(C_DIM / 32, F_DIM / 32), tb>>>(fc2_w, fc2wT, F_DIM, C_DIM, C_DIM);

    // conv-weight projection: 128x256 tiles -> 64 CTAs
    tc_gemm<0, 1><<<dim3(1, M_DIM / 128), 256, smem1>>>(
        mA1, mB1, nullptr, nullptr, wraw, NPAD, C_DIM / BK);

    dynconv_ln_kernel<<<dim3(T_DIM / TT, B_DIM), 512, DC_SMEM>>>(
        x, wraw, b_lin, ln_g, ln_b, y, yrn);

    // fc1 + ReLU: 256x256 tiles
    tc_gemm<1, 2><<<dim3(F_DIM / BN, M_DIM / 256), 256, smem2>>>(
        mA2, mB2, fc1_b, nullptr, h, F_DIM, C_DIM / BK);

    // fc2 + bias + residual
    tc_gemm<2, 2><<<dim3(C_DIM / BN, M_DIM / 256), 256, smem2>>>(
        mA3, mB3, fc2_b, y, out, C_DIM, F_DIM / BK);
}

// round 6
// speedup vs baseline: 1.1477x; 1.0183x over previous
#include <cuda_runtime.h>
#include <cuda.h>
#include <dlfcn.h>
#include <math.h>
#include <stdint.h>

// ---------------- problem constants ----------------
#define T_DIM 1024
#define B_DIM 8
#define C_DIM 1024
#define F_DIM 4096
#define H_DIM 16
#define K_TAPS 15
#define M_DIM (T_DIM * B_DIM)   // 8192
#define NPAD 256
#define LN_EPS 1e-5f

#define BK 32                   // floats per k-chunk (128 bytes per row)

// dynconv tiling
#define TT 32
#define HALO (K_TAPS - 1)
#define XS_ROWS (TT + HALO)
#define DC_SMEM ((XS_ROWS * C_DIM + TT * (H_DIM * K_TAPS) + 64) * 4)

// arch-specific feature gate (tcgen05/multicast only on the sm_103a pass)
#if defined(__CUDA_ARCH_FEAT_SM103_ALL) || defined(__CUDA_ARCH_FEAT_SM100_ALL) || \
    (defined(__CUDA_ARCH_SPECIFIC__) && (__CUDA_ARCH_SPECIFIC__ >= 1000)) ||      \
    (defined(__CUDA_ARCH_FAMILY_SPECIFIC__) && (__CUDA_ARCH_FAMILY_SPECIFIC__ >= 1000))
#define TC_OK 1
#else
#define TC_OK 0
#endif

// ---------------- scratch (device globals) ----------------
__device__ float g_wlinT[NPAD * C_DIM];
__device__ float g_fc1wT[(size_t)F_DIM * C_DIM];
__device__ float g_fc2wT[(size_t)C_DIM * F_DIM];
__device__ float g_wraw[(size_t)M_DIM * NPAD];
__device__ float g_y[(size_t)M_DIM * C_DIM];
__device__ float g_yrn[(size_t)M_DIM * C_DIM];
__device__ float g_h[(size_t)M_DIM * F_DIM];

// ---------------- helpers ----------------
__device__ __forceinline__ float to_tf32(float x) {
    float r;
    asm("cvt.rna.tf32.f32 %0, %1;" : "=f"(r) : "f"(x));
    return r;
}
__device__ __forceinline__ uint32_t smem_u32(const void* p) {
    uint32_t a;
    asm("{ .reg .u64 t; cvta.to.shared.u64 t, %1; cvt.u32.u64 %0, t; }" : "=r"(a) : "l"(p));
    return a;
}
__device__ __forceinline__ uint32_t elect_one() {
    uint32_t p;
    asm volatile("{ .reg .pred p; elect.sync _|p, 0xFFFFFFFF; selp.b32 %0, 1, 0, p; }" : "=r"(p));
    return p;
}
__device__ __forceinline__ void mbar_init(uint32_t a, uint32_t cnt) {
    asm volatile("mbarrier.init.shared.b64 [%0], %1;" :: "r"(a), "r"(cnt) : "memory");
}
__device__ __forceinline__ void mbar_expect_tx(uint32_t a, uint32_t bytes) {
    asm volatile("mbarrier.arrive.expect_tx.shared.b64 _, [%0], %1;" :: "r"(a), "r"(bytes) : "memory");
}
__device__ __forceinline__ void mbar_wait(uint32_t a, uint32_t parity) {
    uint32_t done;
    asm volatile(
        "{ .reg .pred p;\n\t"
        "mbarrier.try_wait.parity.acquire.cta.shared::cta.b64 p, [%1], %2;\n\t"
        "selp.b32 %0, 1, 0, p; }" : "=r"(done) : "r"(a), "r"(parity) : "memory");
    if (!done) {
        asm volatile(
            "{ .reg .pred P1;\n\t"
            "WL_%=:\n\t"
            "mbarrier.try_wait.parity.acquire.cta.shared::cta.b64 P1, [%0], %1, 0x989680;\n\t"
            "@P1 bra.uni WD_%=;\n\t"
            "bra.uni WL_%=;\n\t"
            "WD_%=: }" :: "r"(a), "r"(parity) : "memory");
    }
}
#if TC_OK
__device__ __forceinline__ uint32_t cluster_rank() {
    uint32_t r;
    asm("mov.u32 %0, %%cluster_ctarank;" : "=r"(r));
    return r;
}
__device__ __forceinline__ void mbar_arrive_cluster(uint32_t local_addr, uint32_t target_rank) {
    asm volatile(
        "{ .reg .b32 ra;\n\t"
        "mapa.shared::cluster.u32 ra, %0, %1;\n\t"
        "mbarrier.arrive.shared::cluster.b64 _, [ra]; }"
        :: "r"(local_addr), "r"(target_rank) : "memory");
}
#define CLUSTER_SYNC() do { \
    asm volatile("barrier.cluster.arrive.aligned;" ::: "memory"); \
    asm volatile("barrier.cluster.wait.aligned;" ::: "memory");   \
} while (0)

__device__ __forceinline__ void tma_2d(uint32_t dst, const void* map, int cx, int cy, uint32_t mbar) {
    asm volatile(
        "cp.async.bulk.tensor.2d.shared::cta.global.tile.mbarrier::complete_tx::bytes "
        "[%0], [%1, {%2, %3}], [%4];"
        :: "r"(dst), "l"(map), "r"(cx), "r"(cy), "r"(mbar) : "memory");
}
__device__ __forceinline__ void tma_2d_mcast(uint32_t dst, const void* map, int cx, int cy,
                                             uint32_t mbar, uint16_t mask) {
    asm volatile(
        "cp.async.bulk.tensor.2d.shared::cluster.global.tile.mbarrier::complete_tx::bytes"
        ".multicast::cluster [%0], [%1, {%2, %3}], [%4], %5;"
        :: "r"(dst), "l"(map), "r"(cx), "r"(cy), "r"(mbar), "h"(mask) : "memory");
}
__device__ __forceinline__ void mma_tf32_ss(uint32_t d, uint64_t adesc, uint64_t bdesc,
                                            uint32_t idesc, uint32_t en) {
    asm volatile(
        "{ .reg .pred p;\n\t"
        "setp.ne.u32 p, %4, 0;\n\t"
        "tcgen05.mma.cta_group::1.kind::tf32 [%0], %1, %2, %3, p; }"
        :: "r"(d), "l"(adesc), "l"(bdesc), "r"(idesc), "r"(en) : "memory");
}
__device__ __forceinline__ void tc_commit(uint32_t mbar) {
    asm volatile(
        "tcgen05.commit.cta_group::1.mbarrier::arrive::one.shared::cluster.b64 [%0];"
        :: "r"(mbar) : "memory");
}
#define TC_ALLOC(smem_addr, ncols) \
    asm volatile("tcgen05.alloc.cta_group::1.sync.aligned.shared::cta.b32 [%0], %1;" \
                 :: "r"(smem_addr), "r"(ncols) : "memory")
#define TC_RELINQ() \
    asm volatile("tcgen05.relinquish_alloc_permit.cta_group::1.sync.aligned;")
#define TC_DEALLOC(tmem, ncols) \
    asm volatile("tcgen05.dealloc.cta_group::1.sync.aligned.b32 %0, %1;" :: "r"(tmem), "r"(ncols))
#define TC_FENCE_AFTER()  asm volatile("tcgen05.fence::after_thread_sync;" ::: "memory")
#define TC_WAIT_LD()      asm volatile("tcgen05.wait::ld.sync.aligned;" ::: "memory")
#define TC_LD_X32(r, addr) \
    asm volatile("tcgen05.ld.sync.aligned.32x32b.x32.b32 " \
        "{%0, %1, %2, %3, %4, %5, %6, %7, %8, %9, %10, %11, %12, %13, %14, %15, " \
        " %16, %17, %18, %19, %20, %21, %22, %23, %24, %25, %26, %27, %28, %29, %30, %31}, [%32];" \
        : "=r"((r)[0]), "=r"((r)[1]), "=r"((r)[2]), "=r"((r)[3]), \
          "=r"((r)[4]), "=r"((r)[5]), "=r"((r)[6]), "=r"((r)[7]), \
          "=r"((r)[8]), "=r"((r)[9]), "=r"((r)[10]), "=r"((r)[11]), \
          "=r"((r)[12]), "=r"((r)[13]), "=r"((r)[14]), "=r"((r)[15]), \
          "=r"((r)[16]), "=r"((r)[17]), "=r"((r)[18]), "=r"((r)[19]), \
          "=r"((r)[20]), "=r"((r)[21]), "=r"((r)[22]), "=r"((r)[23]), \
          "=r"((r)[24]), "=r"((r)[25]), "=r"((r)[26]), "=r"((r)[27]), \
          "=r"((r)[28]), "=r"((r)[29]), "=r"((r)[30]), "=r"((r)[31]) \
        : "r"(addr))

__device__ __forceinline__ uint64_t smem_desc_sw128(uint32_t addr) {
    return ((uint64_t)2 << 61) | ((uint64_t)1 << 46) | ((uint64_t)64 << 32) |
           ((uint64_t)1 << 16) | (((uint64_t)addr >> 4) & 0x3FFF);
}
__device__ __forceinline__ constexpr uint32_t idesc_tf32(int bn) {
    return (1u << 4) | (2u << 7) | (2u << 10) | ((uint32_t)(bn / 8) << 17) | (8u << 24);
}
#endif  // TC_OK

// shared epilogue (TC_OK only)
#if TC_OK
template <int EPI, int MH, int BN_>
__device__ __forceinline__ void gemm_epilogue(uint32_t tmem, int tile_m, int tile_n,
                                              const float* __restrict__ bias,
                                              const float* __restrict__ res,
                                              float* __restrict__ C, int N,
                                              int warp, int lane) {
    const int half = warp >> 2;
    uint32_t dbase;
    int row, col0, nchunk;
    if (MH == 2) {
        dbase = tmem + half * BN_;
        row = tile_m + half * 128 + (warp & 3) * 32 + lane;
        col0 = tile_n;
        nchunk = BN_ / 32;
    } else {
        dbase = tmem + half * (BN_ / 2);
        row = tile_m + (warp & 3) * 32 + lane;
        col0 = tile_n + half * (BN_ / 2);
        nchunk = BN_ / 64;
    }
    #pragma unroll 1
    for (int cc = 0; cc < nchunk; cc++) {
        uint32_t r[32];
        TC_LD_X32(r, dbase + cc * 32);
        TC_WAIT_LD();
        const int colbase = col0 + cc * 32;
        float4* dst = reinterpret_cast<float4*>(&C[(size_t)row * N + colbase]);
        #pragma unroll
        for (int j = 0; j < 32; j += 4) {
            float4 v;
            v.x = __uint_as_float(r[j + 0]);
            v.y = __uint_as_float(r[j + 1]);
            v.z = __uint_as_float(r[j + 2]);
            v.w = __uint_as_float(r[j + 3]);
            if (EPI >= 1) {
                v.x += bias[colbase + j + 0]; v.y += bias[colbase + j + 1];
                v.z += bias[colbase + j + 2]; v.w += bias[colbase + j + 3];
            }
            if (EPI == 1) {
                v.x = to_tf32(fmaxf(v.x, 0.f)); v.y = to_tf32(fmaxf(v.y, 0.f));
                v.z = to_tf32(fmaxf(v.z, 0.f)); v.w = to_tf32(fmaxf(v.w, 0.f));
            }
            if (EPI == 2) {
                float4 rv = *reinterpret_cast<const float4*>(&res[(size_t)row * N + colbase + j]);
                v.x += rv.x; v.y += rv.y; v.z += rv.z; v.w += rv.w;
            }
            dst[j / 4] = v;
        }
    }
}
#endif

// ================= plain warp-specialized tcgen05 GEMM (no cluster) =================
template <int EPI, int MH, int BN_, int STG>
__global__ __launch_bounds__(256)
void tc_gemm_plain(const __grid_constant__ CUtensorMap tmA,
                   const __grid_constant__ CUtensorMap tmB,
                   const float* __restrict__ bias, const float* __restrict__ res,
                   float* __restrict__ C, int N, int NC) {
#if TC_OK
    constexpr int BMk = 128 * MH;
    constexpr int CA = BMk * BK * 4;
    constexpr int CB = BN_ * BK * 4;
    constexpr int CBYTES = CA + CB;
    constexpr int TCOLS = BN_ * MH;

    extern __shared__ __align__(1024) char smem[];
    const int tid  = threadIdx.x;
    const int warp = tid >> 5;
    const int lane = tid & 31;

    uint32_t sb = (smem_u32(smem) + 1023u) & ~1023u;
    const uint32_t tmem_ptr_addr = sb;
    const uint32_t mb_all = sb + 8 + 16 * STG;
    uint32_t mb_full[STG], mb_done[STG], bufA[STG], bufB[STG];
    #pragma unroll
    for (int s = 0; s < STG; s++) {
        mb_full[s] = sb + 8 + 8 * s;
        mb_done[s] = sb + 8 + 8 * STG + 8 * s;
        bufA[s] = sb + 1024 + s * CBYTES;
        bufB[s] = bufA[s] + CA;
    }

    if (warp == 0) { TC_ALLOC(tmem_ptr_addr, TCOLS); TC_RELINQ(); }
    if (tid == 0) {
        #pragma unroll
        for (int s = 0; s < STG; s++) { mbar_init(mb_full[s], 1); mbar_init(mb_done[s], 1); }
        mbar_init(mb_all, 1);
    }
    __syncthreads();

    uint32_t tmem;
    asm volatile("ld.shared.b32 %0, [%1];" : "=r"(tmem) : "r"(tmem_ptr_addr));

    const int tile_m = blockIdx.y * BMk;
    const int tile_n = blockIdx.x * BN_;

    if (warp == 1 && elect_one()) {
        // producer
        uint32_t phd = 0;
        for (int j = 0; j < NC; j++) {
            const int s = j % STG;
            if (j >= STG) { mbar_wait(mb_done[s], (phd >> s) & 1); phd ^= 1u << s; }
            mbar_expect_tx(mb_full[s], CBYTES);
            tma_2d(bufA[s], &tmA, j * BK, tile_m, mb_full[s]);
            tma_2d(bufB[s], &tmB, j * BK, tile_n, mb_full[s]);
        }
    }
    if (warp == 0 && elect_one()) {
        // consumer
        uint64_t ad[STG][MH], bd[STG];
        #pragma unroll
        for (int s = 0; s < STG; s++) {
            #pragma unroll
            for (int hh = 0; hh < MH; hh++)
                ad[s][hh] = smem_desc_sw128(bufA[s] + hh * 128 * 128);
            bd[s] = smem_desc_sw128(bufB[s]);
        }
        uint32_t phf = 0;
        for (int kc = 0; kc < NC; kc++) {
            const int s = kc % STG;
            mbar_wait(mb_full[s], (phf >> s) & 1); phf ^= 1u << s;
            #pragma unroll
            for (int s2 = 0; s2 < 4; s2++) {
                const uint32_t en = (kc > 0 || s2 > 0) ? 1u : 0u;
                #pragma unroll
                for (int hh = 0; hh < MH; hh++)
                    mma_tf32_ss(tmem + hh * BN_, ad[s][hh] + 2 * s2, bd[s] + 2 * s2,
                                idesc_tf32(BN_), en);
            }
            tc_commit(mb_done[s]);
        }
        tc_commit(mb_all);
        mbar_wait(mb_all, 0);
    }
    __syncthreads();
    TC_FENCE_AFTER();
    gemm_epilogue<EPI, MH, BN_>(tmem, tile_m, tile_n, bias, res, C, N, warp, lane);
    __syncthreads();
    if (warp == 0) TC_DEALLOC(tmem, TCOLS);
#endif
}

// ================= clustered (2x2) multicast tcgen05 GEMM =================
// Tile 256x256 per CTA, 3-stage ring. A multicast within x-pairs (same tile_m),
// B multicast within y-pairs (same tile_n): halves L2 traffic for BOTH operands.
template <int EPI>
__global__ __launch_bounds__(256) __cluster_dims__(2, 2, 1)
void tc_gemm_c4(const __grid_constant__ CUtensorMap tmA,
                const __grid_constant__ CUtensorMap tmB,
                const float* __restrict__ bias, const float* __restrict__ res,
                float* __restrict__ C, int N, int NC) {
#if TC_OK
    constexpr int STG = 3;
    constexpr int BN_ = 256;
    constexpr int CA = 256 * BK * 4;      // 32 KB
    constexpr int CB = 256 * BK * 4;      // 32 KB
    constexpr int CBYTES = CA + CB;
    constexpr int TCOLS = 512;

    extern __shared__ __align__(1024) char smem[];
    const int tid  = threadIdx.x;
    const int warp = tid >> 5;
    const int lane = tid & 31;

    uint32_t sb = (smem_u32(smem) + 1023u) & ~1023u;
    const uint32_t tmem_ptr_addr = sb;
    uint32_t mb_full[STG], mb_done[STG], mb_eA[STG], mb_eB[STG];
    uint32_t bufA[STG], bufB[STG];
    #pragma unroll
    for (int s = 0; s < STG; s++) {
        mb_full[s] = sb + 8 + 8 * s;        // 8,16,24
        mb_done[s] = sb + 32 + 8 * s;       // 32,40,48
        mb_eA[s]   = sb + 56 + 8 * s;       // 56,64,72
        mb_eB[s]   = sb + 80 + 8 * s;       // 80,88,96
        bufA[s] = sb + 1024 + s * CBYTES;
        bufB[s] = bufA[s] + CA;
    }
    const uint32_t mb_all = sb + 104;

    if (warp == 0) { TC_ALLOC(tmem_ptr_addr, TCOLS); TC_RELINQ(); }
    if (tid == 0) {
        #pragma unroll
        for (int s = 0; s < STG; s++) {
            mbar_init(mb_full[s], 1);
            mbar_init(mb_done[s], 1);
            mbar_init(mb_eA[s], 2);     // arrivals from the 2 CTAs of the x-pair
            mbar_init(mb_eB[s], 2);     // arrivals from the 2 CTAs of the y-pair
        }
        mbar_init(mb_all, 1);
    }
    __syncthreads();
    CLUSTER_SYNC();   // all mbarriers initialized before any cross-CTA arrive / mcast

    uint32_t tmem;
    asm volatile("ld.shared.b32 %0, [%1];" : "=r"(tmem) : "r"(tmem_ptr_addr));

    const uint32_t rank = cluster_rank();    // cx + 2*cy
    const int cx = rank & 1, cy = (int)(rank >> 1);
    const int tile_m = blockIdx.y * 256;
    const int tile_n = blockIdx.x * 256;

    if (warp == 1 && elect_one()) {
        // producer: A issued by cx==0 (mcast to x-pair), B issued by cy==0 (mcast to y-pair)
        const uint16_t maskA = (uint16_t)(0x3u << (2 * cy));          // {0,1} or {2,3}
        const uint16_t maskB = (uint16_t)(cx == 0 ? 0x5u : 0xAu);     // {0,2} or {1,3}
        const uint32_t rankA = (uint32_t)(2 * cy);                    // A-issuer of my x-pair
        const uint32_t rankB = (uint32_t)cx;                          // B-issuer of my y-pair
        uint32_t phd = 0, pheA = 0, pheB = 0;
        for (int j = 0; j < NC; j++) {
            const int s = j % STG;
            if (j >= STG) { mbar_wait(mb_done[s], (phd >> s) & 1); phd ^= 1u << s; }
            mbar_expect_tx(mb_full[s], CBYTES);
            // announce: my stage s is free and my expect_tx is set
            mbar_arrive_cluster(mb_eA[s], rankA);
            mbar_arrive_cluster(mb_eB[s], rankB);
            if (cx == 0) {
                mbar_wait(mb_eA[s], (pheA >> s) & 1); pheA ^= 1u << s;
                tma_2d_mcast(bufA[s], &tmA, j * BK, tile_m, mb_full[s], maskA);
            }
            if (cy == 0) {
                mbar_wait(mb_eB[s], (pheB >> s) & 1); pheB ^= 1u << s;
                tma_2d_mcast(bufB[s], &tmB, j * BK, tile_n, mb_full[s], maskB);
            }
        }
    }
    if (warp == 0 && elect_one()) {
        // consumer
        uint64_t ad[STG][2], bd[STG];
        #pragma unroll
        for (int s = 0; s < STG; s++) {
            ad[s][0] = smem_desc_sw128(bufA[s]);
            ad[s][1] = smem_desc_sw128(bufA[s] + 128 * 128);
            bd[s] = smem_desc_sw128(bufB[s]);
        }
        uint32_t phf = 0;
        for (int kc = 0; kc < NC; kc++) {
            const int s = kc % STG;
            mbar_wait(mb_full[s], (phf >> s) & 1); phf ^= 1u << s;
            #pragma unroll
            for (int s2 = 0; s2 < 4; s2++) {
                const uint32_t en = (kc > 0 || s2 > 0) ? 1u : 0u;
                mma_tf32_ss(tmem,       ad[s][0] + 2 * s2, bd[s] + 2 * s2, idesc_tf32(BN_), en);
                mma_tf32_ss(tmem + 256, ad[s][1] + 2 * s2, bd[s] + 2 * s2, idesc_tf32(BN_), en);
            }
            tc_commit(mb_done[s]);
        }
        tc_commit(mb_all);
        mbar_wait(mb_all, 0);
    }
    __syncthreads();
    TC_FENCE_AFTER();
    gemm_epilogue<EPI, 2, BN_>(tmem, tile_m, tile_n, bias, res, C, N, warp, lane);
    __syncthreads();
    if (warp == 0) TC_DEALLOC(tmem, TCOLS);
    // no CTA may exit while peers might still arrive on its mbarriers
    CLUSTER_SYNC();
#endif
}

// ================= transpose (+pad rows, +tf32 round) =================
__global__ void transpose_rn_kernel(const float* __restrict__ in, float* __restrict__ out,
                                    int R, int Cc, int Cp) {
    __shared__ float tile[32][33];
    const int c0 = blockIdx.x * 32, r0 = blockIdx.y * 32;
    const int x = c0 + threadIdx.x;
    #pragma unroll
    for (int i = 0; i < 32; i += 8) {
        const int y = r0 + threadIdx.y + i;
        float v = 0.f;
        if (x < Cc && y < R) v = in[(size_t)y * Cc + x];
        tile[threadIdx.y + i][threadIdx.x] = v;
    }
    __syncthreads();
    const int ox = r0 + threadIdx.x;
    #pragma unroll
    for (int i = 0; i < 32; i += 8) {
        const int oy = c0 + threadIdx.y + i;
        if (oy < Cp && ox < R)
            out[(size_t)oy * R + ox] = to_tf32(tile[threadIdx.x][threadIdx.y + i]);
    }
}

// ================= t-tiled softmax + causal dynamic conv + LayerNorm =================
__global__ __launch_bounds__(512)
void dynconv_ln_kernel(const float* __restrict__ x, const float* __restrict__ wraw,
                       const float* __restrict__ b_lin,
                       const float* __restrict__ ln_g, const float* __restrict__ ln_b,
                       float* __restrict__ y, float* __restrict__ yrn) {
    extern __shared__ float sm[];
    float* xs  = sm;
    float* ws  = xs + XS_ROWS * C_DIM;
    float* red = ws + TT * (H_DIM * K_TAPS);

    const int t0  = blockIdx.x * TT;
    const int b   = blockIdx.y;
    const int tid = threadIdx.x;

    {
        float4* xs4 = reinterpret_cast<float4*>(xs);
        const int total4 = XS_ROWS * (C_DIM / 4);
        for (int i = tid; i < total4; i += 512) {
            const int r = i / (C_DIM / 4);
            const int cc = i % (C_DIM / 4);
            const int t = t0 - HALO + r;
            float4 v = make_float4(0.f, 0.f, 0.f, 0.f);
            if (t >= 0)
                v = reinterpret_cast<const float4*>(x)[((size_t)(t * B_DIM + b)) * (C_DIM / 4) + cc];
            xs4[i] = v;
        }
    }
    for (int i = tid; i < TT * (H_DIM * K_TAPS); i += 512) {
        const int lt = i / (H_DIM * K_TAPS);
        const int j  = i % (H_DIM * K_TAPS);
        ws[i] = wraw[(size_t)((t0 + lt) * B_DIM + b) * NPAD + j] + b_lin[j];
    }
    __syncthreads();

    {
        const int lt = tid >> 4;
        const int hd = tid & 15;
        float* p = ws + lt * (H_DIM * K_TAPS) + hd * K_TAPS;
        float mx = -1e30f;
        #pragma unroll
        for (int k = 0; k < K_TAPS; k++) mx = fmaxf(mx, p[k]);
        float e[K_TAPS]; float s = 0.f;
        #pragma unroll
        for (int k = 0; k < K_TAPS; k++) { e[k] = expf(p[k] - mx); s += e[k]; }
        const float inv = 1.0f / s;
        #pragma unroll
        for (int k = 0; k < K_TAPS; k++) p[k] = e[k] * inv;
    }
    __syncthreads();

    const int c0 = tid * 2;
    const int h  = c0 >> 6;
    const float g0 = ln_g[c0], g1 = ln_g[c0 + 1];
    const float bb0 = ln_b[c0], bb1 = ln_b[c0 + 1];
    const int wid = tid >> 5, lane = tid & 31;

    for (int lt = 0; lt < TT; lt++) {
        const float* wrow = ws + lt * (H_DIM * K_TAPS) + h * K_TAPS;
        float a0 = 0.f, a1 = 0.f;
        #pragma unroll
        for (int k = 0; k < K_TAPS; k++) {
            const float wgt = wrow[k];
            const float2 xv = *reinterpret_cast<const float2*>(&xs[(lt + k) * C_DIM + c0]);
            a0 += wgt * xv.x;
            a1 += wgt * xv.y;
        }
        float s1 = a0 + a1;
        float s2 = a0 * a0 + a1 * a1;
        #pragma unroll
        for (int off = 16; off > 0; off >>= 1) {
            s1 += __shfl_down_sync(0xFFFFFFFFu, s1, off);
            s2 += __shfl_down_sync(0xFFFFFFFFu, s2, off);
        }
        if (lane == 0) { red[wid] = s1; red[16 + wid] = s2; }
        __syncthreads();
        if (tid == 0) {
            float sa = 0.f, sb2 = 0.f;
            #pragma unroll
            for (int i = 0; i < 16; i++) { sa += red[i]; sb2 += red[16 + i]; }
            const float mu = sa * (1.0f / C_DIM);
            const float var = sb2 * (1.0f / C_DIM) - mu * mu;
            red[32] = mu;
            red[33] = rsqrtf(var + LN_EPS);
        }
        __syncthreads();
        const float mu = red[32], rstd = red[33];
        const float v0 = (a0 - mu) * rstd * g0 + bb0;
        const float v1 = (a1 - mu) * rstd * g1 + bb1;
        const size_t base = (size_t)((t0 + lt) * B_DIM + b) * C_DIM + c0;
        *reinterpret_cast<float2*>(&y[base])   = make_float2(v0, v1);
        *reinterpret_cast<float2*>(&yrn[base]) = make_float2(to_tf32(v0), to_tf32(v1));
    }
}

// ================= host side =================
typedef CUresult (*PFN_encodeTiled)(CUtensorMap*, CUtensorMapDataType, cuuint32_t, void*,
                                    const cuuint64_t*, const cuuint64_t*, const cuuint32_t*,
                                    const cuuint32_t*, CUtensorMapInterleave, CUtensorMapSwizzle,
                                    CUtensorMapL2promotion, CUtensorMapFloatOOBfill);

static PFN_encodeTiled get_encoder() {
    static PFN_encodeTiled fn = nullptr;
    if (!fn) {
        void* h = dlopen("libcuda.so.1", RTLD_LAZY | RTLD_GLOBAL);
        if (!h) h = dlopen("libcuda.so", RTLD_LAZY | RTLD_GLOBAL);
        if (h) fn = (PFN_encodeTiled)dlsym(h, "cuTensorMapEncodeTiled");
    }
    return fn;
}

static void make_map(CUtensorMap* m, const void* ptr, uint64_t d0, uint64_t d1,
                     uint32_t b0, uint32_t b1) {
    cuuint64_t dims[2] = { d0, d1 };
    cuuint64_t strides[1] = { d0 * 4 };
    cuuint32_t box[2] = { b0, b1 };
    cuuint32_t es[2] = { 1, 1 };
    PFN_encodeTiled enc = get_encoder();
    if (enc)
        enc(m, CU_TENSOR_MAP_DATA_TYPE_FLOAT32, 2, (void*)ptr, dims, strides, box, es,
            CU_TENSOR_MAP_INTERLEAVE_NONE, CU_TENSOR_MAP_SWIZZLE_128B,
            CU_TENSOR_MAP_L2_PROMOTION_L2_128B, CU_TENSOR_MAP_FLOAT_OOB_FILL_NONE);
}

extern "C" void kernel_launch(void* const* d_in, const int* in_sizes, int n_in,
                              void* d_out, int out_size) {
    const float* x     = (const float*)d_in[0];
    const float* w_lin = (const float*)d_in[1];
    const float* b_lin = (const float*)d_in[2];
    const float* ln_g  = (const float*)d_in[3];
    const float* ln_b  = (const float*)d_in[4];
    const float* fc1_w = (const float*)d_in[5];
    const float* fc1_b = (const float*)d_in[6];
    const float* fc2_w = (const float*)d_in[7];
    const float* fc2_b = (const float*)d_in[8];
    float* out = (float*)d_out;

    float *wlinT, *fc1wT, *fc2wT, *wraw, *y, *yrn, *h;
    cudaGetSymbolAddress((void**)&wlinT, g_wlinT);
    cudaGetSymbolAddress((void**)&fc1wT, g_fc1wT);
    cudaGetSymbolAddress((void**)&fc2wT, g_fc2wT);
    cudaGetSymbolAddress((void**)&wraw, g_wraw);
    cudaGetSymbolAddress((void**)&y, g_y);
    cudaGetSymbolAddress((void**)&yrn, g_yrn);
    cudaGetSymbolAddress((void**)&h, g_h);

    const int smem_g1 = 1024 + 5 * ((128 * BK + 128 * BK) * 4);   // 5 stages x 32KB
    const int smem_c4 = 1024 + 3 * ((256 * BK + 256 * BK) * 4);   // 3 stages x 64KB
    cudaFuncSetAttribute((const void*)tc_gemm_plain<0, 1, 128, 5>,
                         cudaFuncAttributeMaxDynamicSharedMemorySize, smem_g1);
    cudaFuncSetAttribute((const void*)tc_gemm_c4<1>,
                         cudaFuncAttributeMaxDynamicSharedMemorySize, smem_c4);
    cudaFuncSetAttribute((const void*)tc_gemm_c4<2>,
                         cudaFuncAttributeMaxDynamicSharedMemorySize, smem_c4);
    cudaFuncSetAttribute((const void*)dynconv_ln_kernel,
                         cudaFuncAttributeMaxDynamicSharedMemorySize, DC_SMEM);

    CUtensorMap mA1{}, mB1{}, mA2{}, mB2{}, mA3{}, mB3{};
    make_map(&mA1, x,     C_DIM, M_DIM, BK, 128);
    make_map(&mB1, wlinT, C_DIM, NPAD,  BK, 128);
    make_map(&mA2, yrn,   C_DIM, M_DIM, BK, 256);
    make_map(&mB2, fc1wT, C_DIM, F_DIM, BK, 256);
    make_map(&mA3, h,     F_DIM, M_DIM, BK, 256);
    make_map(&mB3, fc2wT, F_DIM, C_DIM, BK, 256);

    dim3 tb(32, 8);
    transpose_rn_kernel<<<dim3(NPAD / 32, C_DIM / 32), tb>>>(w_lin, wlinT, C_DIM, H_DIM * K_TAPS, NPAD);
    transpose_rn_kernel<<<dim3(F_DIM / 32, C_DIM / 32), tb>>>(fc1_w, fc1wT, C_DIM, F_DIM, F_DIM);
    transpose_rn_kernel<<<dim3(C_DIM / 32, F_DIM / 32), tb>>>(fc2_w, fc2wT, F_DIM, C_DIM, C_DIM);

    // conv-weight projection: 128x128 tiles, 128 CTAs, 5-stage ring
    tc_gemm_plain<0, 1, 128, 5><<<dim3(NPAD / 128, M_DIM / 128), 256, smem_g1>>>(
        mA1, mB1, nullptr, nullptr, wraw, NPAD, C_DIM / BK);

    dynconv_ln_kernel<<<dim3(T_DIM / TT, B_DIM), 512, DC_SMEM>>>(
        x, wraw, b_lin, ln_g, ln_b, y, yrn);

    // fc1 + ReLU: 256x256 tiles, cluster (2,2) multicast
    tc_gemm_c4<1><<<dim3(F_DIM / 256, M_DIM / 256), 256, smem_c4>>>(
        mA2, mB2, fc1_b, nullptr, h, F_DIM, C_DIM / BK);

    // fc2 + bias + residual: cluster (2,2) multicast
    tc_gemm_c4<2><<<dim3(C_DIM / 256, M_DIM / 256), 256, smem_c4>>>(
        mA3, mB3, fc2_b, y, out, C_DIM, F_DIM / BK);
}